// round 3
// baseline (speedup 1.0000x reference)
#include <cuda_runtime.h>
#include <math.h>
#include <float.h>

#define NN 50000
#define NE 500000
#define DD 64
#define NL 4
#define NB_SCAN ((NN + 511) / 512)
#define INV_SQRT_N 0.0044721359549995794f

// ---------------- device buffers ----------------
__device__ float g_PQ[NN * 128];     // [P | Q]
__device__ float g_Xc[NN * 448];     // [h | mean mx mn std var sum]
__device__ float g_G[NN * 192];      // GEMM2 output
__device__ float g_hu[NN * DD];
__device__ float g_C2[NN * DD];
__device__ float g_out[NN * DD];
__device__ float g_bufA[NN * DD];
__device__ float g_bufB[NN * DD];
__device__ int   g_deg[NN];
__device__ int   g_off[NN + 1];
__device__ int   g_cur[NN];
__device__ int   g_srcs[NE];
__device__ int   g_part[128];
__device__ float g_degf[NN];
__device__ float g_amp[NN];
__device__ float g_att[NN];
__device__ float g_s1[DD], g_q1[DD], g_s2[DD], g_q2[DD];
__device__ float g_mu2[DD], g_rs2[DD];
__device__ float g_WMcat[64 * 128];
__device__ float g_Wbig[448 * 192];
__device__ float g_Wp[64 * 64];
__device__ float g_bp[64];

// ---------------- f32x2 helpers ----------------
__device__ __forceinline__ unsigned long long pk2(float lo, float hi) {
    unsigned long long r;
    asm("mov.b64 %0, {%1,%2};" : "=l"(r) : "f"(lo), "f"(hi));
    return r;
}
__device__ __forceinline__ unsigned long long fma2(unsigned long long a,
                                                   unsigned long long b,
                                                   unsigned long long c) {
    unsigned long long d;
    asm("fma.rn.f32x2 %0, %1, %2, %3;" : "=l"(d) : "l"(a), "l"(b), "l"(c));
    return d;
}
__device__ __forceinline__ float2 upk2(unsigned long long a) {
    float2 r;
    asm("mov.b64 {%0,%1}, %2;" : "=f"(r.x), "=f"(r.y) : "l"(a));
    return r;
}

// ---------------- CSR build ----------------
__global__ void k_zero_deg() {
    int i = blockIdx.x * blockDim.x + threadIdx.x;
    if (i < NN) g_deg[i] = 0;
}
__global__ void k_count(const int* __restrict__ dst) {
    int e = blockIdx.x * blockDim.x + threadIdx.x;
    if (e < NE) atomicAdd(&g_deg[dst[e]], 1);
}
__global__ void k_scanA() {
    __shared__ int sd[512];
    int t = threadIdx.x;
    int i = blockIdx.x * 512 + t;
    int v = (i < NN) ? g_deg[i] : 0;
    sd[t] = v;
    __syncthreads();
    for (int o = 1; o < 512; o <<= 1) {
        int x = (t >= o) ? sd[t - o] : 0;
        __syncthreads();
        sd[t] += x;
        __syncthreads();
    }
    if (i < NN) g_off[i] = sd[t];  // inclusive for now
    if (t == 511) g_part[blockIdx.x] = sd[511];
}
__global__ void k_scanB() {
    if (threadIdx.x == 0) {
        int acc = 0;
        for (int b = 0; b < NB_SCAN; b++) {
            int tv = g_part[b];
            g_part[b] = acc;
            acc += tv;
        }
    }
}
__global__ void k_scanC() {
    int t = threadIdx.x;
    int i = blockIdx.x * 512 + t;
    if (i < NN) {
        int d = g_deg[i];
        int excl = g_off[i] + g_part[blockIdx.x] - d;
        g_off[i] = excl;
        g_cur[i] = excl;
        float dg = (float)d;
        g_degf[i] = dg;
        float logD = logf(dg + 1.0f);
        g_amp[i] = logD * (1.0f / 2.5f);
        g_att[i] = (d > 0) ? (2.5f / logD) : 0.0f;
    }
    if (i == 0) g_off[NN] = NE;
}
__global__ void k_fill(const int* __restrict__ src, const int* __restrict__ dst) {
    int e = blockIdx.x * blockDim.x + threadIdx.x;
    if (e < NE) {
        int p = atomicAdd(&g_cur[dst[e]], 1);
        g_srcs[p] = src[e];
    }
}

// ---------------- per-layer weight prep + stats zero ----------------
__global__ void k_prep(const float* __restrict__ WM, const float* __restrict__ WU) {
    int i = blockIdx.x * blockDim.x + threadIdx.x;
    if (i < 64 * 128) {
        int k = i >> 7, j = i & 127;
        g_WMcat[i] = (j < 64) ? WM[k * 64 + j] : WM[(64 + k) * 64 + (j - 64)];
    }
    int i2 = i - 64 * 128;
    if (i2 >= 0 && i2 < 448 * 192) {
        int r = i2 / 192, c = i2 % 192;
        float v;
        if (r < 64) {
            v = (c < 64) ? WU[r * 64 + c] : 0.0f;
        } else {
            int a = r - 64;
            if (c < 64)       v = WU[(64 + a) * 64 + c];
            else if (c < 128) v = WU[(448 + a) * 64 + (c - 64)];
            else              v = WU[(832 + a) * 64 + (c - 128)];
        }
        g_Wbig[i2] = v;
    }
    int i3 = i2 - 448 * 192;
    if (i3 >= 0 && i3 < 64) {
        g_s1[i3] = 0.f; g_q1[i3] = 0.f; g_s2[i3] = 0.f; g_q2[i3] = 0.f;
    }
}

// ---------------- GEMM: C[M x (gridDim.y*64)] = X[M x K] @ W[K x ldw] ----------------
// block tile 256 rows x 64 cols, per-thread 8x8, f32x2 packed FMA
__global__ void __launch_bounds__(256, 2)
k_gemm(const float* __restrict__ X, int ldx,
       const float* __restrict__ W, int ldw,
       float* __restrict__ C, int ldc,
       int M, int K) {
    __shared__ float Xs[16][256];
    __shared__ float Ws[16][64];
    int tid = threadIdx.x;
    int rowBase = blockIdx.x * 256;
    int colBase = blockIdx.y * 64;
    int tr = tid >> 3;      // 0..31 -> 8-row group
    int tc = tid & 7;       // 0..7  -> 8-col group

    unsigned long long acc[8][4];
#pragma unroll
    for (int i = 0; i < 8; i++)
#pragma unroll
        for (int j = 0; j < 4; j++) acc[i][j] = 0ULL;

    int xRow = rowBase + tid;
    int wr = tid >> 4;            // 0..15
    int wc = (tid & 15) * 4;      // 0..60

    for (int kt = 0; kt < K; kt += 16) {
        if (xRow < M) {
            const float4* srcp = (const float4*)(X + (size_t)xRow * ldx + kt);
#pragma unroll
            for (int i = 0; i < 4; i++) {
                float4 v = srcp[i];
                Xs[i * 4 + 0][tid] = v.x;
                Xs[i * 4 + 1][tid] = v.y;
                Xs[i * 4 + 2][tid] = v.z;
                Xs[i * 4 + 3][tid] = v.w;
            }
        } else {
#pragma unroll
            for (int k = 0; k < 16; k++) Xs[k][tid] = 0.0f;
        }
        {
            float4 v = *(const float4*)(W + (size_t)(kt + wr) * ldw + colBase + wc);
            *(float4*)&Ws[wr][wc] = v;
        }
        __syncthreads();
#pragma unroll
        for (int k = 0; k < 16; k++) {
            float4 a0 = *(float4*)&Xs[k][tr * 8];
            float4 a1 = *(float4*)&Xs[k][tr * 8 + 4];
            float4 b0 = *(float4*)&Ws[k][tc * 8];
            float4 b1 = *(float4*)&Ws[k][tc * 8 + 4];
            unsigned long long bb[4];
            bb[0] = pk2(b0.x, b0.y);
            bb[1] = pk2(b0.z, b0.w);
            bb[2] = pk2(b1.x, b1.y);
            bb[3] = pk2(b1.z, b1.w);
            float av[8] = {a0.x, a0.y, a0.z, a0.w, a1.x, a1.y, a1.z, a1.w};
#pragma unroll
            for (int r = 0; r < 8; r++) {
                unsigned long long aa = pk2(av[r], av[r]);
#pragma unroll
                for (int p = 0; p < 4; p++) acc[r][p] = fma2(aa, bb[p], acc[r][p]);
            }
        }
        __syncthreads();
    }
    int r0 = rowBase + tr * 8;
#pragma unroll
    for (int i = 0; i < 8; i++) {
        int r = r0 + i;
        if (r < M) {
            float* crow = C + (size_t)r * ldc + colBase + tc * 8;
#pragma unroll
            for (int p = 0; p < 4; p++) {
                float2 f = upk2(acc[i][p]);
                ((float2*)crow)[p] = f;
            }
        }
    }
}

// ---------------- aggregation (CSR gather) + Xc build ----------------
__global__ void k_agg(const float* __restrict__ h, const float* __restrict__ bM) {
    int v = blockIdx.x * blockDim.y + threadIdx.y;
    if (v >= NN) return;
    int t = threadIdx.x;  // 0..63
    float c = g_PQ[(size_t)v * 128 + 64 + t] + bM[t];
    int beg = g_off[v], end = g_off[v + 1];
    float s = 0.f, sq = 0.f, mx = -FLT_MAX, mn = FLT_MAX;
    for (int e = beg; e < end; e++) {
        int u = g_srcs[e];
        float q = g_PQ[(size_t)u * 128 + t] + c;
        s += q;
        sq += q * q;
        mx = fmaxf(mx, q);
        mn = fminf(mn, q);
    }
    float dg = g_degf[v];
    float dn = fmaxf(dg, 1.0f);
    float mean = s / dn;
    float msq = sq / dn;
    float var = fmaxf(msq - mean * mean, 0.0f);
    float sd = sqrtf(var + 1e-30f);
    bool has = dg > 0.0f;
    float* xr = g_Xc + (size_t)v * 448;
    xr[t]       = h[(size_t)v * 64 + t];
    xr[64 + t]  = mean;
    xr[128 + t] = has ? mx : 0.0f;
    xr[192 + t] = has ? mn : 0.0f;
    xr[256 + t] = sd;
    xr[320 + t] = var;
    xr[384 + t] = s;
}

// ---------------- epilogue A: hu from G, BN1 stats ----------------
__global__ void k_epiA(const float* __restrict__ bU) {
    int j = threadIdx.x;
    float bu = bU[j];
    float ls = 0.f, lq = 0.f;
    for (int v = blockIdx.x * blockDim.y + threadIdx.y; v < NN;
         v += gridDim.x * blockDim.y) {
        const float* g = g_G + (size_t)v * 192;
        float x = (g[j] + g_amp[v] * g[64 + j] + g_att[v] * g[128 + j] + bu) * INV_SQRT_N;
        g_hu[(size_t)v * 64 + j] = x;
        ls += x;
        lq += x * x;
    }
    __shared__ float ss[4][64], sqm[4][64];
    ss[threadIdx.y][j] = ls;
    sqm[threadIdx.y][j] = lq;
    __syncthreads();
    if (threadIdx.y == 0) {
        atomicAdd(&g_s1[j], ss[0][j] + ss[1][j] + ss[2][j] + ss[3][j]);
        atomicAdd(&g_q1[j], sqm[0][j] + sqm[1][j] + sqm[2][j] + sqm[3][j]);
    }
}

// ---------------- BN1 finalize + fold into Wmix ----------------
__global__ void k_fold(const float* __restrict__ gt, const float* __restrict__ bt,
                       const float* __restrict__ Wmix, const float* __restrict__ bmix) {
    __shared__ float sc[64], sh[64];
    int t = threadIdx.x;  // 256
    if (t < 64) {
        float mu = g_s1[t] * (1.0f / NN);
        float var = g_q1[t] * (1.0f / NN) - mu * mu;
        float rs = rsqrtf(var + 1e-5f);
        float c = rs * gt[t];
        sc[t] = c;
        sh[t] = bt[t] - mu * c;
    }
    __syncthreads();
    for (int i = t; i < 4096; i += 256) {
        int k = i >> 6;
        g_Wp[i] = sc[k] * Wmix[i];
    }
    if (t < 64) {
        float b = bmix[t];
        for (int k = 0; k < 64; k++) b += sh[k] * Wmix[k * 64 + t];
        g_bp[t] = b;
    }
}

// ---------------- epilogue B: leaky + residual, BN2 stats ----------------
__global__ void k_epiB(const float* __restrict__ h) {
    int j = threadIdx.x;
    float bp = g_bp[j];
    float ls = 0.f, lq = 0.f;
    for (int v = blockIdx.x * blockDim.y + threadIdx.y; v < NN;
         v += gridDim.x * blockDim.y) {
        float x = g_C2[(size_t)v * 64 + j] + bp;
        x = (x > 0.0f) ? x : 0.01f * x;
        float o = x + h[(size_t)v * 64 + j];
        g_out[(size_t)v * 64 + j] = o;
        ls += o;
        lq += o * o;
    }
    __shared__ float ss[4][64], sqm[4][64];
    ss[threadIdx.y][j] = ls;
    sqm[threadIdx.y][j] = lq;
    __syncthreads();
    if (threadIdx.y == 0) {
        atomicAdd(&g_s2[j], ss[0][j] + ss[1][j] + ss[2][j] + ss[3][j]);
        atomicAdd(&g_q2[j], sqm[0][j] + sqm[1][j] + sqm[2][j] + sqm[3][j]);
    }
}

__global__ void k_bn2() {
    int t = threadIdx.x;
    if (t < 64) {
        float mu = g_s2[t] * (1.0f / NN);
        float var = g_q2[t] * (1.0f / NN) - mu * mu;
        g_mu2[t] = mu;
        g_rs2[t] = rsqrtf(var + 1e-5f);
    }
}

// ---------------- epilogue C: relu(BN2) + residual ----------------
__global__ void k_epiC(const float* __restrict__ h, const float* __restrict__ go,
                       const float* __restrict__ bo, float* __restrict__ hn) {
    int i = blockIdx.x * blockDim.x + threadIdx.x;
    if (i < NN * 64) {
        int j = i & 63;
        float x = (g_out[i] - g_mu2[j]) * g_rs2[j] * go[j] + bo[j];
        x = fmaxf(x, 0.0f);
        hn[i] = x + h[i];
    }
}

// ---------------- host launcher ----------------
extern "C" void kernel_launch(void* const* d_in, const int* in_sizes, int n_in,
                              void* d_out, int out_size) {
    const float* node = (const float*)d_in[0];
    const int* esrc = (const int*)d_in[2];
    const int* edst = (const int*)d_in[3];
    const float* WM = (const float*)d_in[4];
    const float* bM = (const float*)d_in[5];
    const float* WU = (const float*)d_in[6];
    const float* bU = (const float*)d_in[7];
    const float* gt = (const float*)d_in[8];
    const float* bt = (const float*)d_in[9];
    const float* Wmix = (const float*)d_in[10];
    const float* bmix = (const float*)d_in[11];
    const float* go = (const float*)d_in[12];
    const float* bo = (const float*)d_in[13];
    float* outp = (float*)d_out;

    float *pPQ, *pXc, *pG, *phu, *pC2, *pWMcat, *pWbig, *pWp, *pA, *pB;
    cudaGetSymbolAddress((void**)&pPQ, g_PQ);
    cudaGetSymbolAddress((void**)&pXc, g_Xc);
    cudaGetSymbolAddress((void**)&pG, g_G);
    cudaGetSymbolAddress((void**)&phu, g_hu);
    cudaGetSymbolAddress((void**)&pC2, g_C2);
    cudaGetSymbolAddress((void**)&pWMcat, g_WMcat);
    cudaGetSymbolAddress((void**)&pWbig, g_Wbig);
    cudaGetSymbolAddress((void**)&pWp, g_Wp);
    cudaGetSymbolAddress((void**)&pA, g_bufA);
    cudaGetSymbolAddress((void**)&pB, g_bufB);

    // CSR build (graph is identical every call; rebuilt deterministically)
    k_zero_deg<<<(NN + 255) / 256, 256>>>();
    k_count<<<(NE + 255) / 256, 256>>>(edst);
    k_scanA<<<NB_SCAN, 512>>>();
    k_scanB<<<1, 32>>>();
    k_scanC<<<NB_SCAN, 512>>>();
    k_fill<<<(NE + 255) / 256, 256>>>(esrc, edst);

    const int GRX = (NN + 255) / 256;  // 196
    const float* hin = node;
    for (int l = 0; l < NL; l++) {
        float* hout = (l == NL - 1) ? outp : ((l & 1) ? pB : pA);
        k_prep<<<(64 * 128 + 448 * 192 + 64 + 255) / 256, 256>>>(
            WM + (size_t)l * 128 * 64, WU + (size_t)l * 1216 * 64);
        // GEMM1: PQ = h @ WMcat   [N,64]@[64,128]
        k_gemm<<<dim3(GRX, 2), 256>>>(hin, 64, pWMcat, 128, pPQ, 128, NN, 64);
        // aggregation -> Xc
        k_agg<<<(NN + 3) / 4, dim3(64, 4)>>>(hin, bM + (size_t)l * 64);
        // GEMM2: G = Xc @ Wbig   [N,448]@[448,192]
        k_gemm<<<dim3(GRX, 3), 256>>>(pXc, 448, pWbig, 192, pG, 192, NN, 448);
        // hu + BN1 stats
        k_epiA<<<296, dim3(64, 4)>>>(bU + (size_t)l * 64);
        // BN1 fold into Wmix
        k_fold<<<1, 256>>>(gt + (size_t)l * 64, bt + (size_t)l * 64,
                           Wmix + (size_t)l * 64 * 64, bmix + (size_t)l * 64);
        // GEMM3: C2 = hu @ Wp    [N,64]@[64,64]
        k_gemm<<<dim3(GRX, 1), 256>>>(phu, 64, pWp, 64, pC2, 64, NN, 64);
        // leaky + residual + BN2 stats
        k_epiB<<<296, dim3(64, 4)>>>(hin);
        k_bn2<<<1, 64>>>();
        // relu(BN2) + residual -> next h
        k_epiC<<<(NN * 64 + 255) / 256, 256>>>(hin, go + (size_t)l * 64,
                                               bo + (size_t)l * 64, hout);
        hin = hout;
    }
}

// round 4
// speedup vs baseline: 1.1697x; 1.1697x over previous
#include <cuda_runtime.h>
#include <math.h>
#include <float.h>

#define NN 50000
#define NE 500000
#define DD 64
#define NL 4
#define NB_SCAN ((NN + 511) / 512)
#define INV_SQRT_N 0.0044721359549995794f

// ---------------- device buffers ----------------
__device__ float g_PQ[NN * 128];     // [P | Q]
__device__ float g_Xc[NN * 448];     // [h | mean mx mn std var sum]
__device__ float g_hu[NN * DD];
__device__ float g_out[NN * DD];
__device__ float g_bufA[NN * DD];
__device__ float g_bufB[NN * DD];
__device__ int   g_deg[NN];
__device__ int   g_off[NN + 1];
__device__ int   g_cur[NN];
__device__ int   g_srcs[NE];
__device__ int   g_part[128];
__device__ float g_degf[NN];
__device__ float g_amp[NN];
__device__ float g_att[NN];
__device__ float g_s1[DD], g_q1[DD], g_s2[DD], g_q2[DD];
__device__ float g_mu2[DD], g_rs2[DD];
__device__ float g_WMcat[64 * 128];
__device__ float g_Wbig[448 * 192];
__device__ float g_Wp[64 * 64];
__device__ float g_bp[64];

// ---------------- f32x2 helpers ----------------
__device__ __forceinline__ unsigned long long pk2(float lo, float hi) {
    unsigned long long r;
    asm("mov.b64 %0, {%1,%2};" : "=l"(r) : "f"(lo), "f"(hi));
    return r;
}
__device__ __forceinline__ unsigned long long fma2(unsigned long long a,
                                                   unsigned long long b,
                                                   unsigned long long c) {
    unsigned long long d;
    asm("fma.rn.f32x2 %0, %1, %2, %3;" : "=l"(d) : "l"(a), "l"(b), "l"(c));
    return d;
}
__device__ __forceinline__ float2 upk2(unsigned long long a) {
    float2 r;
    asm("mov.b64 {%0,%1}, %2;" : "=f"(r.x), "=f"(r.y) : "l"(a));
    return r;
}
__device__ __forceinline__ int swz(int g) { return g ^ ((g >> 3) & 1); }

// ---------------- CSR build ----------------
__global__ void k_zero_deg() {
    int i = blockIdx.x * blockDim.x + threadIdx.x;
    if (i < NN) g_deg[i] = 0;
}
__global__ void k_count(const int* __restrict__ dst) {
    int e = blockIdx.x * blockDim.x + threadIdx.x;
    if (e < NE) atomicAdd(&g_deg[dst[e]], 1);
}
__global__ void k_scanA() {
    __shared__ int sd[512];
    int t = threadIdx.x;
    int i = blockIdx.x * 512 + t;
    int v = (i < NN) ? g_deg[i] : 0;
    sd[t] = v;
    __syncthreads();
    for (int o = 1; o < 512; o <<= 1) {
        int x = (t >= o) ? sd[t - o] : 0;
        __syncthreads();
        sd[t] += x;
        __syncthreads();
    }
    if (i < NN) g_off[i] = sd[t];  // inclusive for now
    if (t == 511) g_part[blockIdx.x] = sd[511];
}
__global__ void k_scanB() {
    if (threadIdx.x == 0) {
        int acc = 0;
        for (int b = 0; b < NB_SCAN; b++) {
            int tv = g_part[b];
            g_part[b] = acc;
            acc += tv;
        }
    }
}
__global__ void k_scanC() {
    int t = threadIdx.x;
    int i = blockIdx.x * 512 + t;
    if (i < NN) {
        int d = g_deg[i];
        int excl = g_off[i] + g_part[blockIdx.x] - d;
        g_off[i] = excl;
        g_cur[i] = excl;
        float dg = (float)d;
        g_degf[i] = dg;
        float logD = logf(dg + 1.0f);
        g_amp[i] = logD * (1.0f / 2.5f);
        g_att[i] = (d > 0) ? (2.5f / logD) : 0.0f;
    }
    if (i == 0) g_off[NN] = NE;
}
__global__ void k_fill(const int* __restrict__ src, const int* __restrict__ dst) {
    int e = blockIdx.x * blockDim.x + threadIdx.x;
    if (e < NE) {
        int p = atomicAdd(&g_cur[dst[e]], 1);
        g_srcs[p] = src[e];
    }
}

// ---------------- per-layer weight prep + stats zero ----------------
__global__ void k_prep(const float* __restrict__ WM, const float* __restrict__ WU) {
    int i = blockIdx.x * blockDim.x + threadIdx.x;
    if (i < 64 * 128) {
        int k = i >> 7, j = i & 127;
        g_WMcat[i] = (j < 64) ? WM[k * 64 + j] : WM[(64 + k) * 64 + (j - 64)];
    }
    int i2 = i - 64 * 128;
    if (i2 >= 0 && i2 < 448 * 192) {
        int r = i2 / 192, c = i2 % 192;
        float v;
        if (r < 64) {
            v = (c < 64) ? WU[r * 64 + c] : 0.0f;
        } else {
            int a = r - 64;
            if (c < 64)       v = WU[(64 + a) * 64 + c];
            else if (c < 128) v = WU[(448 + a) * 64 + (c - 64)];
            else              v = WU[(832 + a) * 64 + (c - 128)];
        }
        g_Wbig[i2] = v;
    }
    int i3 = i2 - 448 * 192;
    if (i3 >= 0 && i3 < 64) {
        g_s1[i3] = 0.f; g_q1[i3] = 0.f; g_s2[i3] = 0.f; g_q2[i3] = 0.f;
    }
}

// ---------------- generic GEMM (used for GEMM1 only) ----------------
__global__ void __launch_bounds__(256, 2)
k_gemm(const float* __restrict__ X, int ldx,
       const float* __restrict__ W, int ldw,
       float* __restrict__ C, int ldc,
       int M, int K) {
    __shared__ float Xs[16][256];
    __shared__ float Ws[16][64];
    int tid = threadIdx.x;
    int rowBase = blockIdx.x * 256;
    int colBase = blockIdx.y * 64;
    int tr = tid >> 3;
    int tc = tid & 7;

    unsigned long long acc[8][4];
#pragma unroll
    for (int i = 0; i < 8; i++)
#pragma unroll
        for (int j = 0; j < 4; j++) acc[i][j] = 0ULL;

    int xRow = rowBase + tid;
    int wr = tid >> 4;
    int wc = (tid & 15) * 4;

    for (int kt = 0; kt < K; kt += 16) {
        if (xRow < M) {
            const float4* srcp = (const float4*)(X + (size_t)xRow * ldx + kt);
#pragma unroll
            for (int i = 0; i < 4; i++) {
                float4 v = srcp[i];
                Xs[i * 4 + 0][tid] = v.x;
                Xs[i * 4 + 1][tid] = v.y;
                Xs[i * 4 + 2][tid] = v.z;
                Xs[i * 4 + 3][tid] = v.w;
            }
        } else {
#pragma unroll
            for (int k = 0; k < 16; k++) Xs[k][tid] = 0.0f;
        }
        {
            float4 v = *(const float4*)(W + (size_t)(kt + wr) * ldw + colBase + wc);
            *(float4*)&Ws[wr][wc] = v;
        }
        __syncthreads();
#pragma unroll
        for (int k = 0; k < 16; k++) {
            float4 a0 = *(float4*)&Xs[k][tr * 8];
            float4 a1 = *(float4*)&Xs[k][tr * 8 + 4];
            float4 b0 = *(float4*)&Ws[k][tc * 8];
            float4 b1 = *(float4*)&Ws[k][tc * 8 + 4];
            unsigned long long bb[4];
            bb[0] = pk2(b0.x, b0.y);
            bb[1] = pk2(b0.z, b0.w);
            bb[2] = pk2(b1.x, b1.y);
            bb[3] = pk2(b1.z, b1.w);
            float av[8] = {a0.x, a0.y, a0.z, a0.w, a1.x, a1.y, a1.z, a1.w};
#pragma unroll
            for (int r = 0; r < 8; r++) {
                unsigned long long aa = pk2(av[r], av[r]);
#pragma unroll
                for (int p = 0; p < 4; p++) acc[r][p] = fma2(aa, bb[p], acc[r][p]);
            }
        }
        __syncthreads();
    }
    int r0 = rowBase + tr * 8;
#pragma unroll
    for (int i = 0; i < 8; i++) {
        int r = r0 + i;
        if (r < M) {
            float* crow = C + (size_t)r * ldc + colBase + tc * 8;
#pragma unroll
            for (int p = 0; p < 4; p++) {
                float2 f = upk2(acc[i][p]);
                ((float2*)crow)[p] = f;
            }
        }
    }
}

// ---------------- aggregation (CSR gather) + Xc build ----------------
__global__ void k_agg(const float* __restrict__ h, const float* __restrict__ bM) {
    int v = blockIdx.x * blockDim.y + threadIdx.y;
    if (v >= NN) return;
    int t = threadIdx.x;  // 0..63
    float c = g_PQ[(size_t)v * 128 + 64 + t] + bM[t];
    int beg = g_off[v], end = g_off[v + 1];
    float s = 0.f, sq = 0.f, mx = -FLT_MAX, mn = FLT_MAX;
    for (int e = beg; e < end; e++) {
        int u = g_srcs[e];
        float q = g_PQ[(size_t)u * 128 + t] + c;
        s += q;
        sq += q * q;
        mx = fmaxf(mx, q);
        mn = fminf(mn, q);
    }
    float dg = g_degf[v];
    float dn = fmaxf(dg, 1.0f);
    float mean = s / dn;
    float msq = sq / dn;
    float var = fmaxf(msq - mean * mean, 0.0f);
    float sd = sqrtf(var + 1e-30f);
    bool has = dg > 0.0f;
    float* xr = g_Xc + (size_t)v * 448;
    xr[t]       = h[(size_t)v * 64 + t];
    xr[64 + t]  = mean;
    xr[128 + t] = has ? mx : 0.0f;
    xr[192 + t] = has ? mn : 0.0f;
    xr[256 + t] = sd;
    xr[320 + t] = var;
    xr[384 + t] = s;
}

// ---------------- fused GEMM2 + scaler epilogue + BN1 stats ----------------
// C[128 x 192] per block, 256 threads, per-thread 8 rows x 12 cols.
// Column ownership {c, c+64, c+128} so the amp/att combine is thread-local.
__global__ void __launch_bounds__(256, 1)
k_gemm2f(const float* __restrict__ bU) {
    __shared__ float As[16 * 128];
    __shared__ float Ws[16][192];
    __shared__ float redS[16][64];
    __shared__ float redQ[16][64];
    int tid = threadIdx.x;
    int rowBase = blockIdx.x * 128;
    int rowg = tid & 15;
    int colg = tid >> 4;
    int cb = colg * 4;

    unsigned long long acc[8][6];
#pragma unroll
    for (int r = 0; r < 8; r++)
#pragma unroll
        for (int p = 0; p < 6; p++) acc[r][p] = 0ULL;

    int g0s = swz(rowg * 2);
    int g1s = swz(rowg * 2 + 1);

    for (int kt = 0; kt < 448; kt += 16) {
        // stage A (transposed, swizzled): As[k][row]
#pragma unroll
        for (int i = 0; i < 2; i++) {
            int idx = i * 256 + tid;
            int row = idx & 127;
            int kq = idx >> 7;  // 0..3
            float4 v = make_float4(0.f, 0.f, 0.f, 0.f);
            int gr = rowBase + row;
            if (gr < NN)
                v = *(const float4*)(g_Xc + (size_t)gr * 448 + kt + kq * 4);
            int sgrp = swz(row >> 2) * 4 + (row & 3);
            As[(kq * 4 + 0) * 128 + sgrp] = v.x;
            As[(kq * 4 + 1) * 128 + sgrp] = v.y;
            As[(kq * 4 + 2) * 128 + sgrp] = v.z;
            As[(kq * 4 + 3) * 128 + sgrp] = v.w;
        }
        // stage B: Ws[k][col], 16x192
#pragma unroll
        for (int i = 0; i < 3; i++) {
            int j = i * 256 + tid;
            int k = j / 48;
            int c4 = j % 48;
            *(float4*)&Ws[k][c4 * 4] =
                *(const float4*)(g_Wbig + (size_t)(kt + k) * 192 + c4 * 4);
        }
        __syncthreads();
#pragma unroll
        for (int k = 0; k < 16; k++) {
            const float4* ak = (const float4*)(As + k * 128);
            float4 a0 = ak[g0s];
            float4 a1 = ak[g1s];
            ulonglong2 b0 = *(const ulonglong2*)&Ws[k][cb];
            ulonglong2 b1 = *(const ulonglong2*)&Ws[k][cb + 64];
            ulonglong2 b2 = *(const ulonglong2*)&Ws[k][cb + 128];
            unsigned long long bb[6] = {b0.x, b0.y, b1.x, b1.y, b2.x, b2.y};
            float av[8] = {a0.x, a0.y, a0.z, a0.w, a1.x, a1.y, a1.z, a1.w};
#pragma unroll
            for (int r = 0; r < 8; r++) {
                unsigned long long aa = pk2(av[r], av[r]);
#pragma unroll
                for (int p = 0; p < 6; p++) acc[r][p] = fma2(aa, bb[p], acc[r][p]);
            }
        }
        __syncthreads();
    }

    // epilogue: hu = (G0 + amp*G1 + att*G2 + bU) * (1/sqrt(N)); BN1 stats
    float4 buv = *(const float4*)&bU[cb];
    float ls0 = 0.f, ls1 = 0.f, ls2 = 0.f, ls3 = 0.f;
    float lq0 = 0.f, lq1 = 0.f, lq2 = 0.f, lq3 = 0.f;
#pragma unroll
    for (int r = 0; r < 8; r++) {
        int row = rowBase + rowg * 8 + r;
        if (row < NN) {
            float amp = g_amp[row];
            float att = g_att[row];
            float2 p0 = upk2(acc[r][0]), p1 = upk2(acc[r][1]);
            float2 q0 = upk2(acc[r][2]), q1 = upk2(acc[r][3]);
            float2 s0 = upk2(acc[r][4]), s1 = upk2(acc[r][5]);
            float x0 = (p0.x + amp * q0.x + att * s0.x + buv.x) * INV_SQRT_N;
            float x1 = (p0.y + amp * q0.y + att * s0.y + buv.y) * INV_SQRT_N;
            float x2 = (p1.x + amp * q1.x + att * s1.x + buv.z) * INV_SQRT_N;
            float x3 = (p1.y + amp * q1.y + att * s1.y + buv.w) * INV_SQRT_N;
            float4 o = make_float4(x0, x1, x2, x3);
            *(float4*)&g_hu[(size_t)row * 64 + cb] = o;
            ls0 += x0; lq0 += x0 * x0;
            ls1 += x1; lq1 += x1 * x1;
            ls2 += x2; lq2 += x2 * x2;
            ls3 += x3; lq3 += x3 * x3;
        }
    }
    redS[rowg][cb + 0] = ls0; redQ[rowg][cb + 0] = lq0;
    redS[rowg][cb + 1] = ls1; redQ[rowg][cb + 1] = lq1;
    redS[rowg][cb + 2] = ls2; redQ[rowg][cb + 2] = lq2;
    redS[rowg][cb + 3] = ls3; redQ[rowg][cb + 3] = lq3;
    __syncthreads();
    if (tid < 64) {
        float s = 0.f, q = 0.f;
#pragma unroll
        for (int g = 0; g < 16; g++) { s += redS[g][tid]; q += redQ[g][tid]; }
        atomicAdd(&g_s1[tid], s);
        atomicAdd(&g_q1[tid], q);
    }
}

// ---------------- BN1 finalize + fold into Wmix ----------------
__global__ void k_fold(const float* __restrict__ gt, const float* __restrict__ bt,
                       const float* __restrict__ Wmix, const float* __restrict__ bmix) {
    __shared__ float sc[64], sh[64];
    int t = threadIdx.x;  // 256
    if (t < 64) {
        float mu = g_s1[t] * (1.0f / NN);
        float var = g_q1[t] * (1.0f / NN) - mu * mu;
        float rs = rsqrtf(var + 1e-5f);
        float c = rs * gt[t];
        sc[t] = c;
        sh[t] = bt[t] - mu * c;
    }
    __syncthreads();
    for (int i = t; i < 4096; i += 256) {
        int k = i >> 6;
        g_Wp[i] = sc[k] * Wmix[i];
    }
    if (t < 64) {
        float b = bmix[t];
        for (int k = 0; k < 64; k++) b += sh[k] * Wmix[k * 64 + t];
        g_bp[t] = b;
    }
}

// ---------------- fused GEMM3 + leaky + residual + BN2 stats ----------------
// C[128 x 64] per block, 256 threads, per-thread 8 rows x 4 cols, K=64.
__global__ void __launch_bounds__(256, 1)
k_gemm3f(const float* __restrict__ h) {
    __shared__ float As[16 * 128];
    __shared__ float Bs[64][64];
    __shared__ float redS[16][64];
    __shared__ float redQ[16][64];
    int tid = threadIdx.x;
    int rowBase = blockIdx.x * 128;
    int rowg = tid & 15;
    int colg = tid >> 4;
    int cb = colg * 4;

    // load whole B (64x64)
#pragma unroll
    for (int i = 0; i < 4; i++) {
        int j = i * 256 + tid;
        int k = j >> 4;
        int c4 = j & 15;
        *(float4*)&Bs[k][c4 * 4] = *(const float4*)(g_Wp + k * 64 + c4 * 4);
    }

    unsigned long long acc[8][2];
#pragma unroll
    for (int r = 0; r < 8; r++) { acc[r][0] = 0ULL; acc[r][1] = 0ULL; }

    int g0s = swz(rowg * 2);
    int g1s = swz(rowg * 2 + 1);

    for (int kt = 0; kt < 64; kt += 16) {
#pragma unroll
        for (int i = 0; i < 2; i++) {
            int idx = i * 256 + tid;
            int row = idx & 127;
            int kq = idx >> 7;
            float4 v = make_float4(0.f, 0.f, 0.f, 0.f);
            int gr = rowBase + row;
            if (gr < NN)
                v = *(const float4*)(g_hu + (size_t)gr * 64 + kt + kq * 4);
            int sgrp = swz(row >> 2) * 4 + (row & 3);
            As[(kq * 4 + 0) * 128 + sgrp] = v.x;
            As[(kq * 4 + 1) * 128 + sgrp] = v.y;
            As[(kq * 4 + 2) * 128 + sgrp] = v.z;
            As[(kq * 4 + 3) * 128 + sgrp] = v.w;
        }
        __syncthreads();
#pragma unroll
        for (int k = 0; k < 16; k++) {
            const float4* ak = (const float4*)(As + k * 128);
            float4 a0 = ak[g0s];
            float4 a1 = ak[g1s];
            ulonglong2 b = *(const ulonglong2*)&Bs[kt + k][cb];
            float av[8] = {a0.x, a0.y, a0.z, a0.w, a1.x, a1.y, a1.z, a1.w};
#pragma unroll
            for (int r = 0; r < 8; r++) {
                unsigned long long aa = pk2(av[r], av[r]);
                acc[r][0] = fma2(aa, b.x, acc[r][0]);
                acc[r][1] = fma2(aa, b.y, acc[r][1]);
            }
        }
        __syncthreads();
    }

    // epilogue: leaky(x + bp) + h residual; BN2 stats
    float4 bp4 = *(const float4*)&g_bp[cb];
    float ls0 = 0.f, ls1 = 0.f, ls2 = 0.f, ls3 = 0.f;
    float lq0 = 0.f, lq1 = 0.f, lq2 = 0.f, lq3 = 0.f;
#pragma unroll
    for (int r = 0; r < 8; r++) {
        int row = rowBase + rowg * 8 + r;
        if (row < NN) {
            float2 p0 = upk2(acc[r][0]);
            float2 p1 = upk2(acc[r][1]);
            float x0 = p0.x + bp4.x;
            float x1 = p0.y + bp4.y;
            float x2 = p1.x + bp4.z;
            float x3 = p1.y + bp4.w;
            x0 = (x0 > 0.f) ? x0 : 0.01f * x0;
            x1 = (x1 > 0.f) ? x1 : 0.01f * x1;
            x2 = (x2 > 0.f) ? x2 : 0.01f * x2;
            x3 = (x3 > 0.f) ? x3 : 0.01f * x3;
            float4 hv = *(const float4*)(h + (size_t)row * 64 + cb);
            float o0 = x0 + hv.x, o1 = x1 + hv.y, o2 = x2 + hv.z, o3 = x3 + hv.w;
            *(float4*)&g_out[(size_t)row * 64 + cb] = make_float4(o0, o1, o2, o3);
            ls0 += o0; lq0 += o0 * o0;
            ls1 += o1; lq1 += o1 * o1;
            ls2 += o2; lq2 += o2 * o2;
            ls3 += o3; lq3 += o3 * o3;
        }
    }
    redS[rowg][cb + 0] = ls0; redQ[rowg][cb + 0] = lq0;
    redS[rowg][cb + 1] = ls1; redQ[rowg][cb + 1] = lq1;
    redS[rowg][cb + 2] = ls2; redQ[rowg][cb + 2] = lq2;
    redS[rowg][cb + 3] = ls3; redQ[rowg][cb + 3] = lq3;
    __syncthreads();
    if (tid < 64) {
        float s = 0.f, q = 0.f;
#pragma unroll
        for (int g = 0; g < 16; g++) { s += redS[g][tid]; q += redQ[g][tid]; }
        atomicAdd(&g_s2[tid], s);
        atomicAdd(&g_q2[tid], q);
    }
}

__global__ void k_bn2() {
    int t = threadIdx.x;
    if (t < 64) {
        float mu = g_s2[t] * (1.0f / NN);
        float var = g_q2[t] * (1.0f / NN) - mu * mu;
        g_mu2[t] = mu;
        g_rs2[t] = rsqrtf(var + 1e-5f);
    }
}

// ---------------- epilogue C: relu(BN2) + residual ----------------
__global__ void k_epiC(const float* __restrict__ h, const float* __restrict__ go,
                       const float* __restrict__ bo, float* __restrict__ hn) {
    int i = blockIdx.x * blockDim.x + threadIdx.x;
    if (i < NN * 64) {
        int j = i & 63;
        float x = (g_out[i] - g_mu2[j]) * g_rs2[j] * go[j] + bo[j];
        x = fmaxf(x, 0.0f);
        hn[i] = x + h[i];
    }
}

// ---------------- host launcher ----------------
extern "C" void kernel_launch(void* const* d_in, const int* in_sizes, int n_in,
                              void* d_out, int out_size) {
    const float* node = (const float*)d_in[0];
    const int* esrc = (const int*)d_in[2];
    const int* edst = (const int*)d_in[3];
    const float* WM = (const float*)d_in[4];
    const float* bM = (const float*)d_in[5];
    const float* WU = (const float*)d_in[6];
    const float* bU = (const float*)d_in[7];
    const float* gt = (const float*)d_in[8];
    const float* bt = (const float*)d_in[9];
    const float* Wmix = (const float*)d_in[10];
    const float* bmix = (const float*)d_in[11];
    const float* go = (const float*)d_in[12];
    const float* bo = (const float*)d_in[13];
    float* outp = (float*)d_out;

    float *pPQ, *pWMcat, *pA, *pB;
    cudaGetSymbolAddress((void**)&pPQ, g_PQ);
    cudaGetSymbolAddress((void**)&pWMcat, g_WMcat);
    cudaGetSymbolAddress((void**)&pA, g_bufA);
    cudaGetSymbolAddress((void**)&pB, g_bufB);

    // CSR build (graph identical every call; rebuilt deterministically)
    k_zero_deg<<<(NN + 255) / 256, 256>>>();
    k_count<<<(NE + 255) / 256, 256>>>(edst);
    k_scanA<<<NB_SCAN, 512>>>();
    k_scanB<<<1, 32>>>();
    k_scanC<<<NB_SCAN, 512>>>();
    k_fill<<<(NE + 255) / 256, 256>>>(esrc, edst);

    const int GRX = (NN + 255) / 256;   // 196 (GEMM1 row tiles)
    const int GR2 = (NN + 127) / 128;   // 391 (GEMM2/3 row tiles)
    const float* hin = node;
    for (int l = 0; l < NL; l++) {
        float* hout = (l == NL - 1) ? outp : ((l & 1) ? pB : pA);
        k_prep<<<(64 * 128 + 448 * 192 + 64 + 255) / 256, 256>>>(
            WM + (size_t)l * 128 * 64, WU + (size_t)l * 1216 * 64);
        // GEMM1: PQ = h @ WMcat   [N,64]@[64,128]
        k_gemm<<<dim3(GRX, 2), 256>>>(hin, 64, pWMcat, 128, pPQ, 128, NN, 64);
        // aggregation -> Xc
        k_agg<<<(NN + 3) / 4, dim3(64, 4)>>>(hin, bM + (size_t)l * 64);
        // fused GEMM2 + scalers + bias + snorm + BN1 stats -> g_hu
        k_gemm2f<<<GR2, 256>>>(bU + (size_t)l * 64);
        // BN1 fold into Wmix
        k_fold<<<1, 256>>>(gt + (size_t)l * 64, bt + (size_t)l * 64,
                           Wmix + (size_t)l * 64 * 64, bmix + (size_t)l * 64);
        // fused GEMM3 + leaky + residual + BN2 stats -> g_out
        k_gemm3f<<<GR2, 256>>>(hin);
        k_bn2<<<1, 64>>>();
        // relu(BN2) + residual -> next h
        k_epiC<<<(NN * 64 + 255) / 256, 256>>>(hin, go + (size_t)l * 64,
                                               bo + (size_t)l * 64, hout);
        hin = hout;
    }
}